// round 14
// baseline (speedup 1.0000x reference)
#include <cuda_runtime.h>
#include <cstdint>
#include <cstddef>

#define NPG 111
#define NB  128
#define EPG (NPG * (NPG - 1))   // 12210
#define PD  113                 // ea row pitch (float2): conflict-free strided access
#define NT  448
#define NWC 14                  // warps per CTA; rows d_local = w + 14r, r=0..3
#define LOG2E 1.4426950408889634f

__device__ __forceinline__ float wredsum(float v) {
#pragma unroll
    for (int o = 16; o; o >>= 1) v += __shfl_xor_sync(0xffffffffu, v, o);
    return v;
}
__device__ __forceinline__ float ex2f(float x) {
    float r; asm("ex2.approx.ftz.f32 %0, %1;" : "=f"(r) : "f"(x)); return r;
}
// store into the peer CTA's smem at the same offset
__device__ __forceinline__ void st_peer(float* p, float v, uint32_t peer) {
    uint32_t a = (uint32_t)__cvta_generic_to_shared(p), ra;
    asm volatile("mapa.shared::cluster.u32 %0, %1, %2;" : "=r"(ra) : "r"(a), "r"(peer));
    asm volatile("st.shared::cluster.f32 [%0], %1;" :: "r"(ra), "f"(v));
}
#define CLUSTER_SYNC() do { \
    asm volatile("barrier.cluster.arrive.aligned;" ::: "memory"); \
    asm volatile("barrier.cluster.wait.aligned;" ::: "memory"); } while (0)

// ---------------------------------------------------------------------------
// Whole network; cluster of 2 CTAs per graph (448 threads each), 2 CTAs/SM.
// Rank-1 collapse: node state is a scalar per layer. Each CTA owns 56 dst
// rows and their d-major ea half in smem. Per layer: warp per dst row
// (4 rows/warp), score+softmax+matvec in registers (log2-domain, bare EX2),
// z-scalars exchanged with the peer CTA via DSMEM + cluster.sync.
// ---------------------------------------------------------------------------
__global__ void __launch_bounds__(NT, 2) __cluster_dims__(2, 1, 1)
fused_all(const float* __restrict__ x,   const float* __restrict__ ea,
          const float* __restrict__ W0,  const float* __restrict__ as0,
          const float* __restrict__ ad0, const float* __restrict__ We0,
          const float* __restrict__ ae0, const float* __restrict__ b0,
          const float* __restrict__ W1,  const float* __restrict__ as1,
          const float* __restrict__ ad1, const float* __restrict__ We1,
          const float* __restrict__ ae1, const float* __restrict__ b1,
          const float* __restrict__ W2,  const float* __restrict__ as2,
          const float* __restrict__ ad2, const float* __restrict__ We2,
          const float* __restrict__ ae2, const float* __restrict__ b2,
          const float* __restrict__ linW, const float* __restrict__ linb,
          float* __restrict__ out)
{
    extern __shared__ float sm[];
    float2* ea2 = (float2*)sm;             // [56*PD] my dst rows, d-major
    float* xs   = sm + 2 * 56 * PD;        // [112] full node scalars
    float* ys   = xs + 112;                // [112]
    float* hs2  = ys + 112;                // [112]
    float* hd2  = hs2 + 112;               // [112]
    float* ctr  = hd2 + 112;               // [112]
    float* colx = ctr + 112;               // [56] my rows' ea sums
    float* coly = colx + 56;               // [56]
    float* wsum = coly + 56;               // [16] per-warp head partials
    float* w01v = wsum + 16;               // [32] W0@W1
    float* Bv   = w01v + 32;               // [32] b0@W1 + b1
    float* usv  = Bv + 32;                 // [32] W2@as2
    float* udv  = usv + 32;                // [32] W2@ad2
    float* vvv  = udv + 32;                // [32] W2@linW
    float* sc   = vvv + 32;                // [16] scalars
    float* pg   = sc + 16;                 // [2] head partials (rank0 only reads)

    const int bid = blockIdx.x;
    const int g   = bid >> 1;
    const uint32_t rank = bid & 1;         // == cluster rank (cluster = bid pairs)
    const uint32_t peer = rank ^ 1;
    const int d_base = rank ? 56 : 0;
    const int nrows  = rank ? 55 : 56;
    const int tid  = threadIdx.x;
    const int lane = tid & 31;
    const int w    = tid >> 5;

    // ============ pass 1 (warp-specialized, fully concurrent) ==============
    if (w >= 6) {
        // ---- ea copy: warps 6..13 read full range, keep my d-half ----
        const int ct = tid - 192;          // 0..255
        const float4* __restrict__ ea4 = (const float4*)ea + (size_t)g * (EPG / 2);
#pragma unroll 4
        for (int i = ct; i < EPG / 2; i += 256) {
            float4 v = ea4[i];
            int e0 = 2 * i;
            int s0 = e0 / 110, dp0 = e0 - s0 * 110;
            int d0 = dp0 + (dp0 >= s0);
            int s1 = s0 + (dp0 == 109);
            int dp1 = (dp0 == 109) ? 0 : dp0 + 1;
            int d1 = dp1 + (dp1 >= s1);
            if ((unsigned)(d0 - d_base) < (unsigned)nrows)
                ea2[(d0 - d_base) * PD + s0] = make_float2(v.x, v.y);
            if ((unsigned)(d1 - d_base) < (unsigned)nrows)
                ea2[(d1 - d_base) * PD + s1] = make_float2(v.z, v.w);
        }
    } else if (w == 5) {
        for (int j = lane; j < 112; j += 32)
            xs[j] = (j < NPG) ? x[g * NPG + j] : 0.f;
        for (int jl = lane; jl < nrows; jl += 32)
            ea2[jl * PD + d_base + jl] = make_float2(0.f, 0.f);   // diagonal
    } else if (w == 0) {   // w01 = W0@W1, bW = b0@W1, B; layer-1 affine coeffs
        float a = 0.f, bb = 0.f;
#pragma unroll
        for (int k = 0; k < 32; k++) {
            float wv = W1[k * 32 + lane];
            a += W0[k] * wv; bb += b0[k] * wv;
        }
        w01v[lane] = a; Bv[lane] = bb + b1[lane];
        float c1 = wredsum(a * as1[lane]);                 // w01.as1
        float c3 = wredsum(a * ad1[lane]);                 // w01.ad1
        float cc = wredsum(bb * (as1[lane] + ad1[lane]));  // bW.(as1+ad1)
        if (lane == 0) { sc[9] = c1; sc[10] = c3; sc[11] = cc; }
    } else if (w == 1) {   // us = W2@as2, ud = W2@ad2, vv = W2@linW
        float u = 0.f, dd = 0.f, vv = 0.f;
#pragma unroll
        for (int c = 0; c < 32; c++) {
            float wv = W2[lane * 32 + c];
            u += wv * as2[c]; dd += wv * ad2[c]; vv += wv * linW[c];
        }
        usv[lane] = u; udv[lane] = dd; vvv[lane] = vv;
    } else if (w == 2) {   // edge-dot pairs, layers 0 & 1
        float p0 = wredsum(We0[lane] * ae0[lane]);
        float p1 = wredsum(We0[32 + lane] * ae0[lane]);
        float p2 = wredsum(We1[lane] * ae1[lane]);
        float p3 = wredsum(We1[32 + lane] * ae1[lane]);
        if (lane == 0) { sc[0] = p0; sc[1] = p1; sc[2] = p2; sc[3] = p3; }
    } else if (w == 3) {   // layer-2 edge pair + layer-0 affine coeffs
        float p4 = wredsum(We2[lane] * ae2[lane]);
        float p5 = wredsum(We2[32 + lane] * ae2[lane]);
        float p6 = wredsum(W0[lane] * as0[lane]);
        float p7 = wredsum(W0[lane] * ad0[lane]);
        if (lane == 0) { sc[4] = p4; sc[5] = p5; sc[6] = p6; sc[7] = p7; }
    } else if (w == 4) {   // b2 . linW
        float p8 = wredsum(b2[lane] * linW[lane]);
        if (lane == 0) sc[8] = p8;
    }
    __syncthreads();       // everything above is CTA-local

    // One-pass layer over my rows dl = w + 14r (r=0..3), dg = d_base + dl.
    // All score constants pre-scaled by log2(e) -> bare ex2. The diagonal
    // element (s==dg) gets the mean-incoming-ea correction (ea2 diag == 0).
    // num/den reductions deferred across rows; EPILOG sees z in ALL lanes.
#define LAYER_PASS(Ap, CA, CC, Bp, CB, WE0c, WE1c, Vp, FIRST, EPILOG)          \
    {                                                                          \
        const float we0c = (WE0c) * LOG2E, we1c = (WE1c) * LOG2E;              \
        const float cav = (CA) * LOG2E, cbv = (CB) * LOG2E,                    \
                    ccv = (CC) * LOG2E;                                        \
        const float ac0 = Ap[lane] * cav, ac1 = Ap[lane + 32] * cav,           \
                    ac2 = Ap[lane + 64] * cav;                                 \
        const float ac3 = (lane < 15) ? Ap[lane + 96] * cav : 0.f;             \
        const float vv0 = Vp[lane], vv1 = Vp[lane + 32], vv2 = Vp[lane + 64];  \
        const float vv3 = (lane < 15) ? Vp[lane + 96] : 0.f;                   \
        float nm[4], dn[4];                                                    \
        _Pragma("unroll")                                                      \
        for (int r = 0; r < 4; r++) {                                          \
            const int dl = w + NWC * r;                                        \
            if (dl >= nrows) break;              /* warp-uniform */            \
            const int dg = d_base + dl;                                        \
            const float2* __restrict__ rp = ea2 + dl * PD;                     \
            float2 e0 = rp[lane];                                              \
            float2 e1 = rp[lane + 32];                                         \
            float2 e2 = rp[lane + 64];                                         \
            float2 e3 = (lane < 15) ? rp[lane + 96] : make_float2(0.f, 0.f);   \
            float corr;                                                        \
            if (FIRST) {                                                       \
                float cx = wredsum(e0.x + e1.x + e2.x + e3.x);                 \
                float cy = wredsum(e0.y + e1.y + e2.y + e3.y);                 \
                if (lane == 0) { colx[dl] = cx; coly[dl] = cy; }               \
                corr = (cx * we0c + cy * we1c) * (1.f / 110.f);                \
            } else {                                                           \
                corr = (colx[dl] * we0c + coly[dl] * we1c) * (1.f / 110.f);    \
            }                                                                  \
            const float bd = Bp[dg] * cbv + ccv;                               \
            float r0 = ac0 + bd + e0.x * we0c + e0.y * we1c;                   \
            float r1 = ac1 + bd + e1.x * we0c + e1.y * we1c;                   \
            float r2 = ac2 + bd + e2.x * we0c + e2.y * we1c;                   \
            float r3 = ac3 + bd + e3.x * we0c + e3.y * we1c;                   \
            r0 += (lane == dg)      ? corr : 0.f;                              \
            r1 += (lane + 32 == dg) ? corr : 0.f;                              \
            r2 += (lane + 64 == dg) ? corr : 0.f;                              \
            r3 += (lane + 96 == dg) ? corr : 0.f;                              \
            r0 = (r0 > 0.f) ? r0 : 0.2f * r0;                                  \
            r1 = (r1 > 0.f) ? r1 : 0.2f * r1;                                  \
            r2 = (r2 > 0.f) ? r2 : 0.2f * r2;                                  \
            r3 = (r3 > 0.f) ? r3 : 0.2f * r3;                                  \
            float p0 = ex2f(r0), p1 = ex2f(r1), p2 = ex2f(r2);                 \
            float p3 = (lane < 15) ? ex2f(r3) : 0.f;                           \
            nm[r] = p0 * vv0 + p1 * vv1 + p2 * vv2 + p3 * vv3;                 \
            dn[r] = p0 + p1 + p2 + p3;                                         \
        }                                                                      \
        _Pragma("unroll")                                                      \
        for (int r = 0; r < 4; r++) {                                          \
            const int dl = w + NWC * r;                                        \
            if (dl >= nrows) break;                                            \
            const int dg = d_base + dl;                                        \
            float num = wredsum(nm[r]);                                        \
            float den = wredsum(dn[r]);                                        \
            float z = num / den;             /* valid in ALL lanes */          \
            EPILOG;                                                            \
        }                                                                      \
    }

    // ======= LAYER 0 (also produces my rows' ea sums) =======
    LAYER_PASS(xs, sc[6], 0.f, xs, sc[7], sc[0], sc[1], xs, 1,
        { if (lane == 0) { ys[dg] = z; st_peer(&ys[dg], z, peer); } });
    CLUSTER_SYNC();

    // ======= LAYER 1 (+ fused layer-2 per-node scalars) =======
    LAYER_PASS(ys, sc[9], sc[11], ys, sc[10], sc[2], sc[3], ys, 0,
        {
            float h = fmaxf(z * w01v[lane] + Bv[lane], 0.f);
            float t0 = wredsum(h * usv[lane]);
            float t1 = wredsum(h * udv[lane]);
            float t2 = wredsum(h * vvv[lane]);
            if (lane == 0) {
                hs2[dg] = t0; hd2[dg] = t1; ctr[dg] = t2;
                st_peer(&hs2[dg], t0, peer);
                st_peer(&hd2[dg], t1, peer);
                st_peer(&ctr[dg], t2, peer);
            }
        });
    CLUSTER_SYNC();

    // ======= LAYER 2 (per-warp head partials) =======
    {
        float qacc = 0.f;
        LAYER_PASS(hs2, 1.f, 0.f, hd2, 1.f, sc[4], sc[5], ctr, 0,
            { qacc += z; });
        if (lane == 0) wsum[w] = qacc;
    }
    __syncthreads();
    if (w == 0) {
        float t = wredsum((lane < NWC) ? wsum[lane] : 0.f);
        if (lane == 0) {
            if (rank == 0) pg[0] = t;
            else          st_peer(&pg[1], t, 0u);
        }
    }
    CLUSTER_SYNC();

    // ======= head: rank0 writes out[g] =======
    if (rank == 0 && tid == 0) {
        float v = pg[0] + pg[1] + 111.f * sc[8] + linb[0];
        out[g] = (v > 0.f) ? v : 0.f;
    }
#undef LAYER_PASS
}

static constexpr int SMEM_FLOATS =
    2 * 56 * PD + 5 * 112 + 2 * 56 + 16 + 5 * 32 + 16 + 2;
static constexpr int SMEM_BYTES = SMEM_FLOATS * 4;   // ~54.1 KB per CTA

extern "C" void kernel_launch(void* const* d_in, const int* in_sizes, int n_in,
                              void* d_out, int out_size)
{
    const float* x    = (const float*)d_in[0];
    // d_in[1] = edge_index: structure fully determined, never read.
    const float* ea   = (const float*)d_in[2];

    const float* W0  = (const float*)d_in[3];
    const float* as0 = (const float*)d_in[4];
    const float* ad0 = (const float*)d_in[5];
    const float* We0 = (const float*)d_in[6];
    const float* ae0 = (const float*)d_in[7];
    const float* b0  = (const float*)d_in[8];

    const float* W1  = (const float*)d_in[9];
    const float* as1 = (const float*)d_in[10];
    const float* ad1 = (const float*)d_in[11];
    const float* We1 = (const float*)d_in[12];
    const float* ae1 = (const float*)d_in[13];
    const float* b1  = (const float*)d_in[14];

    const float* W2  = (const float*)d_in[15];
    const float* as2 = (const float*)d_in[16];
    const float* ad2 = (const float*)d_in[17];
    const float* We2 = (const float*)d_in[18];
    const float* ae2 = (const float*)d_in[19];
    const float* b2  = (const float*)d_in[20];

    const float* linW = (const float*)d_in[21];
    const float* linb = (const float*)d_in[22];
    float* out = (float*)d_out;

    cudaFuncSetAttribute(fused_all, cudaFuncAttributeMaxDynamicSharedMemorySize, SMEM_BYTES);
    fused_all<<<NB * 2, NT, SMEM_BYTES>>>(x, ea,
                                          W0, as0, ad0, We0, ae0, b0,
                                          W1, as1, ad1, We1, ae1, b1,
                                          W2, as2, ad2, We2, ae2, b2,
                                          linW, linb, out);
}

// round 15
// speedup vs baseline: 1.1518x; 1.1518x over previous
#include <cuda_runtime.h>
#include <cstdint>
#include <cstddef>

#define NPG 111
#define NB  128
#define EPG (NPG * (NPG - 1))   // 12210
#define PD  113                 // plane pitch: odd -> conflict-free scatter stores
#define NT  896
#define NW  28                  // rows d = w + 28r, r=0..3 (only w=27,r=3 skips)
#define LOG2E 1.4426950408889634f

__device__ __forceinline__ float wredsum(float v) {
#pragma unroll
    for (int o = 16; o; o >>= 1) v += __shfl_xor_sync(0xffffffffu, v, o);
    return v;
}
__device__ __forceinline__ float ex2f(float x) {
    float r; asm("ex2.approx.ftz.f32 %0, %1;" : "=f"(r) : "f"(x)); return r;
}

// ---------------------------------------------------------------------------
// Whole network, one block per graph, 896 threads (28 warps).
// Rank-1 collapse: node state is a scalar per layer. The ONLY per-edge data
// each layer needs is edot_l = (ea . we_l); all three are precomputed in the
// copy phase (hidden under DRAM latency) into 3 scalar smem planes, d-major,
// pre-scaled by log2(e) -> layers use bare EX2. Self-loop (mean incoming ea)
// correction = row-sum of the plane / 110 (diag slots are 0), computed as a
// deferred warp reduction from the already-loaded row.
// ---------------------------------------------------------------------------
__global__ void __launch_bounds__(NT, 1)
fused_all(const float* __restrict__ x,   const float* __restrict__ ea,
          const float* __restrict__ W0,  const float* __restrict__ as0,
          const float* __restrict__ ad0, const float* __restrict__ We0,
          const float* __restrict__ ae0, const float* __restrict__ b0,
          const float* __restrict__ W1,  const float* __restrict__ as1,
          const float* __restrict__ ad1, const float* __restrict__ We1,
          const float* __restrict__ ae1, const float* __restrict__ b1,
          const float* __restrict__ W2,  const float* __restrict__ as2,
          const float* __restrict__ ad2, const float* __restrict__ We2,
          const float* __restrict__ ae2, const float* __restrict__ b2,
          const float* __restrict__ linW, const float* __restrict__ linb,
          float* __restrict__ out)
{
    extern __shared__ float sm[];
    float* p0s = sm;                       // [NPG*PD] edot layer0 * LOG2E
    float* p1s = p0s + NPG * PD;           // [NPG*PD] edot layer1 * LOG2E
    float* p2s = p1s + NPG * PD;           // [NPG*PD] edot layer2 * LOG2E
    float* xs  = p2s + NPG * PD;           // [112]
    float* ys  = xs + 112;
    float* hs2 = ys + 112;
    float* hd2 = hs2 + 112;
    float* ctr = hd2 + 112;
    float* wsum = ctr + 112;               // [32] per-warp head partials
    float* w01v = wsum + 32;               // [32] W0@W1
    float* Bv   = w01v + 32;               // [32] b0@W1 + b1
    float* usv  = Bv + 32;                 // [32] W2@as2
    float* udv  = usv + 32;                // [32] W2@ad2
    float* vvv  = udv + 32;                // [32] W2@linW
    float* sc   = vvv + 32;                // [16] scalars (we pairs LOG2E-scaled)

    const int g    = blockIdx.x;
    const int tid  = threadIdx.x;
    const int lane = tid & 31;
    const int w    = tid >> 5;

    // ============ pre-phase: weight constants (warps 0-4), xs+diag (warp 5) =
    if (w == 0) {          // w01 = W0@W1, bW = b0@W1, B; layer-1 affine coeffs
        float a = 0.f, bb = 0.f;
#pragma unroll
        for (int k = 0; k < 32; k++) {
            float wv = W1[k * 32 + lane];
            a += W0[k] * wv; bb += b0[k] * wv;
        }
        w01v[lane] = a; Bv[lane] = bb + b1[lane];
        float c1 = wredsum(a * as1[lane]);                 // w01.as1
        float c3 = wredsum(a * ad1[lane]);                 // w01.ad1
        float cc = wredsum(bb * (as1[lane] + ad1[lane]));  // bW.(as1+ad1)
        if (lane == 0) { sc[9] = c1; sc[10] = c3; sc[11] = cc; }
    } else if (w == 1) {   // us = W2@as2, ud = W2@ad2, vv = W2@linW
        float u = 0.f, dd = 0.f, vv = 0.f;
#pragma unroll
        for (int c = 0; c < 32; c++) {
            float wv = W2[lane * 32 + c];
            u += wv * as2[c]; dd += wv * ad2[c]; vv += wv * linW[c];
        }
        usv[lane] = u; udv[lane] = dd; vvv[lane] = vv;
    } else if (w == 2) {   // we pairs layers 0,1 (pre-scaled by LOG2E)
        float p0 = wredsum(We0[lane] * ae0[lane]);
        float p1 = wredsum(We0[32 + lane] * ae0[lane]);
        float p2 = wredsum(We1[lane] * ae1[lane]);
        float p3 = wredsum(We1[32 + lane] * ae1[lane]);
        if (lane == 0) {
            sc[0] = p0 * LOG2E; sc[1] = p1 * LOG2E;
            sc[2] = p2 * LOG2E; sc[3] = p3 * LOG2E;
        }
    } else if (w == 3) {   // we pair layer2 (scaled) + layer-0 affine coeffs
        float p4 = wredsum(We2[lane] * ae2[lane]);
        float p5 = wredsum(We2[32 + lane] * ae2[lane]);
        float p6 = wredsum(W0[lane] * as0[lane]);
        float p7 = wredsum(W0[lane] * ad0[lane]);
        if (lane == 0) {
            sc[4] = p4 * LOG2E; sc[5] = p5 * LOG2E;
            sc[6] = p6; sc[7] = p7;
        }
    } else if (w == 4) {   // b2 . linW
        float p8 = wredsum(b2[lane] * linW[lane]);
        if (lane == 0) sc[8] = p8;
    } else if (w == 5) {   // xs + plane diagonals (copy never writes s==d)
        for (int j = lane; j < 112; j += 32)
            xs[j] = (j < NPG) ? x[g * NPG + j] : 0.f;
        for (int j = lane; j < NPG; j += 32) {
            p0s[j * PD + j] = 0.f;
            p1s[j * PD + j] = 0.f;
            p2s[j * PD + j] = 0.f;
        }
    }
    __syncthreads();

    // ============ copy phase: all 896 threads, 7-deep batch, 3 edots =======
    {
        const float w00 = sc[0], w10 = sc[1];
        const float w01c = sc[2], w11c = sc[3];
        const float w02c = sc[4], w12c = sc[5];
        const float4* __restrict__ ea4 = (const float4*)ea + (size_t)g * (EPG / 2);
        float4 vbuf[7];
#pragma unroll
        for (int k = 0; k < 6; k++) vbuf[k] = ea4[tid + 896 * k];
        const bool p6 = tid < (EPG / 2 - 5376);
        vbuf[6] = p6 ? ea4[tid + 5376] : make_float4(0.f, 0.f, 0.f, 0.f);
#pragma unroll
        for (int k = 0; k < 7; k++) {
            if (k == 6 && !p6) break;
            const int i = tid + 896 * k;
            const float4 v = vbuf[k];
            int e0 = 2 * i;
            int s0 = e0 / 110, dp0 = e0 - s0 * 110;
            int d0 = dp0 + (dp0 >= s0);
            int s1 = s0 + (dp0 == 109);
            int dp1 = (dp0 == 109) ? 0 : dp0 + 1;
            int d1 = dp1 + (dp1 >= s1);
            const int o0 = d0 * PD + s0, o1 = d1 * PD + s1;
            p0s[o0] = v.x * w00  + v.y * w10;
            p1s[o0] = v.x * w01c + v.y * w11c;
            p2s[o0] = v.x * w02c + v.y * w12c;
            p0s[o1] = v.z * w00  + v.w * w10;
            p1s[o1] = v.z * w01c + v.w * w11c;
            p2s[o1] = v.z * w02c + v.w * w12c;
        }
    }
    __syncthreads();

    // One-pass layer over rows d = w + 28r, r=0..3.
    // raw(s,d)*log2e = Ap[s]*CA' + CC' + Bp[d]*CB' + plane[d][s]; the diagonal
    // gets csum/110 (csum = warp row-sum; diag slot is 0). Reductions deferred
    // across rows; EPILOG sees z = num/den in ALL lanes.
#define LAYER_PASS(Ap, CA, CC, Bp, CB, PL, Vp, EPILOG)                         \
    {                                                                          \
        const float cav = (CA) * LOG2E, cbv = (CB) * LOG2E,                    \
                    ccv = (CC) * LOG2E;                                        \
        const float ac0 = Ap[lane] * cav, ac1 = Ap[lane + 32] * cav,           \
                    ac2 = Ap[lane + 64] * cav;                                 \
        const float ac3 = (lane < 15) ? Ap[lane + 96] * cav : 0.f;             \
        const float vv0 = Vp[lane], vv1 = Vp[lane + 32], vv2 = Vp[lane + 64];  \
        const float vv3 = (lane < 15) ? Vp[lane + 96] : 0.f;                   \
        float nm[4], dn[4];                                                    \
        _Pragma("unroll")                                                      \
        for (int r = 0; r < 4; r++) {                                          \
            const int d = w + NW * r;                                          \
            if (d >= NPG) break;                 /* warp-uniform (w==27) */    \
            const float* __restrict__ rp = PL + d * PD;                        \
            float e0 = rp[lane];                                               \
            float e1 = rp[lane + 32];                                          \
            float e2 = rp[lane + 64];                                          \
            float e3 = (lane < 15) ? rp[lane + 96] : 0.f;                      \
            float corr = wredsum(e0 + e1 + e2 + e3) * (1.f / 110.f);           \
            const float bd = Bp[d] * cbv + ccv;                                \
            float r0 = ac0 + bd + e0;                                          \
            float r1 = ac1 + bd + e1;                                          \
            float r2 = ac2 + bd + e2;                                          \
            float r3 = ac3 + bd + e3;                                          \
            r0 += (lane == d)      ? corr : 0.f;                               \
            r1 += (lane + 32 == d) ? corr : 0.f;                               \
            r2 += (lane + 64 == d) ? corr : 0.f;                               \
            r3 += (lane + 96 == d) ? corr : 0.f;                               \
            r0 = fmaxf(r0, 0.2f * r0);                                         \
            r1 = fmaxf(r1, 0.2f * r1);                                         \
            r2 = fmaxf(r2, 0.2f * r2);                                         \
            r3 = fmaxf(r3, 0.2f * r3);                                         \
            float q0 = ex2f(r0), q1 = ex2f(r1), q2 = ex2f(r2);                 \
            float q3 = (lane < 15) ? ex2f(r3) : 0.f;                           \
            nm[r] = q0 * vv0 + q1 * vv1 + q2 * vv2 + q3 * vv3;                 \
            dn[r] = q0 + q1 + q2 + q3;                                         \
        }                                                                      \
        _Pragma("unroll")                                                      \
        for (int r = 0; r < 4; r++) {                                          \
            const int d = w + NW * r;                                          \
            if (d >= NPG) break;                                               \
            float num = wredsum(nm[r]);                                        \
            float den = wredsum(dn[r]);                                        \
            float z = num / den;             /* valid in ALL lanes */          \
            EPILOG;                                                            \
        }                                                                      \
    }

    // ======= LAYER 0 =======
    LAYER_PASS(xs, sc[6], 0.f, xs, sc[7], p0s, xs,
        { if (lane == 0) ys[d] = z; });
    __syncthreads();

    // ======= LAYER 1 (+ fused layer-2 per-node scalars) =======
    LAYER_PASS(ys, sc[9], sc[11], ys, sc[10], p1s, ys,
        {
            float h = fmaxf(z * w01v[lane] + Bv[lane], 0.f);
            float t0 = wredsum(h * usv[lane]);
            float t1 = wredsum(h * udv[lane]);
            float t2 = wredsum(h * vvv[lane]);
            if (lane == 0) { hs2[d] = t0; hd2[d] = t1; ctr[d] = t2; }
        });
    __syncthreads();

    // ======= LAYER 2 (per-warp head partials) =======
    {
        float qacc = 0.f;
        LAYER_PASS(hs2, 1.f, 0.f, hd2, 1.f, p2s, ctr,
            { qacc += z; });
        if (lane == 0) wsum[w] = qacc;
    }
    __syncthreads();

    // ======= head: out[g] = relu( sum + 111*(b2.linW) + linb ) =======
    if (w == 0) {
        float t = wredsum((lane < NW) ? wsum[lane] : 0.f);
        if (lane == 0) {
            float v = t + 111.f * sc[8] + linb[0];
            out[g] = (v > 0.f) ? v : 0.f;
        }
    }
#undef LAYER_PASS
}

static constexpr int SMEM_FLOATS =
    3 * NPG * PD + 5 * 112 + 32 + 5 * 32 + 16;
static constexpr int SMEM_BYTES = SMEM_FLOATS * 4;   // ~150 KB

extern "C" void kernel_launch(void* const* d_in, const int* in_sizes, int n_in,
                              void* d_out, int out_size)
{
    const float* x    = (const float*)d_in[0];
    // d_in[1] = edge_index: structure fully determined, never read.
    const float* ea   = (const float*)d_in[2];

    const float* W0  = (const float*)d_in[3];
    const float* as0 = (const float*)d_in[4];
    const float* ad0 = (const float*)d_in[5];
    const float* We0 = (const float*)d_in[6];
    const float* ae0 = (const float*)d_in[7];
    const float* b0  = (const float*)d_in[8];

    const float* W1  = (const float*)d_in[9];
    const float* as1 = (const float*)d_in[10];
    const float* ad1 = (const float*)d_in[11];
    const float* We1 = (const float*)d_in[12];
    const float* ae1 = (const float*)d_in[13];
    const float* b1  = (const float*)d_in[14];

    const float* W2  = (const float*)d_in[15];
    const float* as2 = (const float*)d_in[16];
    const float* ad2 = (const float*)d_in[17];
    const float* We2 = (const float*)d_in[18];
    const float* ae2 = (const float*)d_in[19];
    const float* b2  = (const float*)d_in[20];

    const float* linW = (const float*)d_in[21];
    const float* linb = (const float*)d_in[22];
    float* out = (float*)d_out;

    cudaFuncSetAttribute(fused_all, cudaFuncAttributeMaxDynamicSharedMemorySize, SMEM_BYTES);
    fused_all<<<NB, NT, SMEM_BYTES>>>(x, ea,
                                      W0, as0, ad0, We0, ae0, b0,
                                      W1, as1, ad1, We1, ae1, b1,
                                      W2, as2, ad2, We2, ae2, b2,
                                      linW, linb, out);
}

// round 17
// speedup vs baseline: 1.3214x; 1.1473x over previous
#include <cuda_runtime.h>
#include <cstdint>
#include <cstddef>

#define NPG 111
#define NB  128
#define EPG (NPG * (NPG - 1))   // 12210
#define PD  113                 // plane pitch: odd -> conflict-free scatter stores
#define NT  896
#define NW  28
#define LOG2E 1.4426950408889634f

__device__ __forceinline__ float wredsum(float v) {
#pragma unroll
    for (int o = 16; o; o >>= 1) v += __shfl_xor_sync(0xffffffffu, v, o);
    return v;
}
// 8-lane segmented reduction (independent per 8-lane group)
__device__ __forceinline__ float segred8(float v) {
    v += __shfl_xor_sync(0xffffffffu, v, 1);
    v += __shfl_xor_sync(0xffffffffu, v, 2);
    v += __shfl_xor_sync(0xffffffffu, v, 4);
    return v;
}
__device__ __forceinline__ float ex2f(float x) {
    float r; asm("ex2.approx.ftz.f32 %0, %1;" : "=f"(r) : "f"(x)); return r;
}

// ---------------------------------------------------------------------------
// Whole network, one block per graph, 896 threads (28 warps).
// Rank-1 collapse: node state is a scalar per layer. 3 edot planes (ea.we_l,
// LOG2E-scaled, d-major) built once in the copy phase. SEGMENTED layer pass:
// warp's 4 dst rows map to its four 8-lane segments, so every softmax/matvec
// reduction is a 3-step segmented butterfly serving 4 rows at once (~50 SHFL
// per warp total vs ~240 in the row-sequential version). Self-loop correction
// comes free from the plane row-sum (diag and pad slots are 0).
// ---------------------------------------------------------------------------
__global__ void __launch_bounds__(NT, 1)
fused_all(const float* __restrict__ x,   const float* __restrict__ ea,
          const float* __restrict__ W0,  const float* __restrict__ as0,
          const float* __restrict__ ad0, const float* __restrict__ We0,
          const float* __restrict__ ae0, const float* __restrict__ b0,
          const float* __restrict__ W1,  const float* __restrict__ as1,
          const float* __restrict__ ad1, const float* __restrict__ We1,
          const float* __restrict__ ae1, const float* __restrict__ b1,
          const float* __restrict__ W2,  const float* __restrict__ as2,
          const float* __restrict__ ad2, const float* __restrict__ We2,
          const float* __restrict__ ae2, const float* __restrict__ b2,
          const float* __restrict__ linW, const float* __restrict__ linb,
          float* __restrict__ out)
{
    extern __shared__ float sm[];
    float* p0s = sm;                       // [112*PD] edot layer0 * LOG2E
    float* p1s = p0s + 112 * PD;           // [112*PD] edot layer1 * LOG2E
    float* p2s = p1s + 112 * PD;           // [112*PD] edot layer2 * LOG2E
    float* xs  = p2s + 112 * PD;           // [112]
    float* ys  = xs + 112;
    float* hs2 = ys + 112;
    float* hd2 = hs2 + 112;
    float* ctr = hd2 + 112;
    float* wsum = ctr + 112;               // [32]
    float* w01v = wsum + 32;               // [32] W0@W1
    float* Bv   = w01v + 32;               // [32] b0@W1 + b1
    float* usv  = Bv + 32;                 // [32] W2@as2
    float* udv  = usv + 32;                // [32] W2@ad2
    float* vvv  = udv + 32;                // [32] W2@linW
    float* sc   = vvv + 32;                // [16] scalars

    const int g    = blockIdx.x;
    const int tid  = threadIdx.x;
    const int lane = tid & 31;
    const int w    = tid >> 5;
    const int seg  = lane >> 3;            // 0..3 -> row within warp
    const int sub  = lane & 7;             // 0..7 -> position in segment

    // ---- issue all ea loads FIRST (hide the constants pre-phase) ----
    const float4* __restrict__ ea4 = (const float4*)ea + (size_t)g * (EPG / 2);
    float4 vbuf[7];
#pragma unroll
    for (int k = 0; k < 6; k++) vbuf[k] = ea4[tid + 896 * k];
    const bool p6 = tid < (EPG / 2 - 5376);
    vbuf[6] = p6 ? ea4[tid + 5376] : make_float4(0.f, 0.f, 0.f, 0.f);

    // ---- pre-phase: constants (warps 0-4), zero-fill (warps 5-7) ----
    if (w == 0) {          // w01 = W0@W1, bW = b0@W1, B; layer-1 affine coeffs
        float a = 0.f;
        float bb = 0.f;
#pragma unroll
        for (int k = 0; k < 32; k++) {
            float wv = W1[k * 32 + lane];
            a += W0[k] * wv; bb += b0[k] * wv;
        }
        w01v[lane] = a; Bv[lane] = bb + b1[lane];
        float c1 = wredsum(a * as1[lane]);
        float c3 = wredsum(a * ad1[lane]);
        float cc = wredsum(bb * (as1[lane] + ad1[lane]));
        if (lane == 0) { sc[9] = c1; sc[10] = c3; sc[11] = cc; }
    } else if (w == 1) {   // us = W2@as2, ud = W2@ad2, vv = W2@linW
        float u = 0.f;
        float dd = 0.f;
        float vv = 0.f;
#pragma unroll
        for (int c = 0; c < 32; c++) {
            float wv = W2[lane * 32 + c];
            u += wv * as2[c]; dd += wv * ad2[c]; vv += wv * linW[c];
        }
        usv[lane] = u; udv[lane] = dd; vvv[lane] = vv;
    } else if (w == 2) {   // we pairs layers 0,1 (pre-scaled by LOG2E)
        float p0 = wredsum(We0[lane] * ae0[lane]);
        float p1 = wredsum(We0[32 + lane] * ae0[lane]);
        float p2 = wredsum(We1[lane] * ae1[lane]);
        float p3 = wredsum(We1[32 + lane] * ae1[lane]);
        if (lane == 0) {
            sc[0] = p0 * LOG2E; sc[1] = p1 * LOG2E;
            sc[2] = p2 * LOG2E; sc[3] = p3 * LOG2E;
        }
    } else if (w == 3) {   // we pair layer2 (scaled) + layer-0 affine coeffs
        float p4 = wredsum(We2[lane] * ae2[lane]);
        float p5 = wredsum(We2[32 + lane] * ae2[lane]);
        float p6c = wredsum(W0[lane] * as0[lane]);
        float p7 = wredsum(W0[lane] * ad0[lane]);
        if (lane == 0) {
            sc[4] = p4 * LOG2E; sc[5] = p5 * LOG2E;
            sc[6] = p6c; sc[7] = p7;
        }
    } else if (w == 4) {   // b2 . linW
        float p8 = wredsum(b2[lane] * linW[lane]);
        if (lane == 0) sc[8] = p8;
    } else if (w == 5) {   // node-scalar arrays + their pads
        for (int j = lane; j < 112; j += 32)
            xs[j] = (j < NPG) ? x[g * NPG + j] : 0.f;
        if (lane == 0) { ys[111] = 0.f; hs2[111] = 0.f; hd2[111] = 0.f; ctr[111] = 0.f; }
        if (lane < 28) wsum[lane] = 0.f;
    } else if (w == 6) {   // plane diagonals = 0 (copy never writes s==d)
        for (int j = lane; j < NPG; j += 32) {
            p0s[j * PD + j] = 0.f; p1s[j * PD + j] = 0.f; p2s[j * PD + j] = 0.f;
        }
    } else if (w == 7) {   // plane pad column s=111 = 0
        for (int j = lane; j < NPG; j += 32) {
            p0s[j * PD + 111] = 0.f; p1s[j * PD + 111] = 0.f; p2s[j * PD + 111] = 0.f;
        }
    }
    __syncthreads();

    // ---- copy phase: edots from prefetched registers ----
    {
        const float w00 = sc[0];
        const float w10 = sc[1];
        const float w01c = sc[2];
        const float w11c = sc[3];
        const float w02c = sc[4];
        const float w12c = sc[5];
#pragma unroll
        for (int k = 0; k < 7; k++) {
            if (k == 6 && !p6) break;
            const int i = tid + 896 * k;
            const float4 v = vbuf[k];
            int e0 = 2 * i;
            int s0 = e0 / 110;
            int dp0 = e0 - s0 * 110;
            int d0 = dp0 + (dp0 >= s0);
            int s1 = s0 + (dp0 == 109);
            int dp1 = (dp0 == 109) ? 0 : dp0 + 1;
            int d1 = dp1 + (dp1 >= s1);
            const int o0 = d0 * PD + s0;
            const int o1 = d1 * PD + s1;
            p0s[o0] = v.x * w00  + v.y * w10;
            p1s[o0] = v.x * w01c + v.y * w11c;
            p2s[o0] = v.x * w02c + v.y * w12c;
            p0s[o1] = v.z * w00  + v.w * w10;
            p1s[o1] = v.z * w01c + v.w * w11c;
            p2s[o1] = v.z * w02c + v.w * w12c;
        }
    }
    __syncthreads();

    // Segmented layer pass. Row d = w + 28*seg (seg = lane/8); lane covers
    // s = sub + 8j, j=0..13. raw*log2e = Ap[s]*cav + (Bp[d]*cbv + ccv) +
    // plane[d][s]. Diag & pad slots are 0 and masked out of num/den; the
    // self-loop term is added after corr = rowsum/110 (segmented reduce).
    // z = num/den lands in all 8 lanes of the segment. EPILOG via __VA_ARGS__
    // so commas inside it are safe.
    const int d      = w + NW * seg;              // 0..111 (111 = dummy row)
    const bool dok   = (d < NPG);
    const int diag_j = d >> 3;
    const bool dlane = (sub == (d & 7));

#define LAYER_PASS(Ap, CA, CC, Bp, CB, PL, Vp, ...)                            \
    {                                                                          \
        const float cav = (CA);                                                \
        const float cbv = (CB);                                                \
        const float ccv = (CC);                                                \
        const float bd = Bp[d] * cbv + ccv;                                    \
        const float* __restrict__ rp = PL + d * PD;                            \
        float rsum = 0.f;                                                      \
        float num = 0.f;                                                       \
        float den = 0.f;                                                       \
        _Pragma("unroll")                                                      \
        for (int j = 0; j < 14; j++) {                                         \
            const int s = sub + 8 * j;                                         \
            const float pv = rp[s];                                            \
            const float av = Ap[s];                                            \
            const float vv = Vp[s];                                            \
            rsum += pv;                                                        \
            float raw = av * cav + bd + pv;                                    \
            raw = fmaxf(raw, 0.2f * raw);                                      \
            float e = ex2f(raw);                                               \
            const bool skip = (dlane && j == diag_j) || (j == 13 && sub == 7); \
            e = skip ? 0.f : e;                                                \
            num += e * vv;                                                     \
            den += e;                                                          \
        }                                                                      \
        rsum = segred8(rsum);                                                  \
        {   /* self-loop (mean incoming edot) term */                          \
            float rawd = Ap[d] * cav + bd + rsum * (1.f / 110.f);              \
            rawd = fmaxf(rawd, 0.2f * rawd);                                   \
            float ed = ex2f(rawd);                                             \
            if (sub == 0) { num += ed * Vp[d]; den += ed; }                    \
        }                                                                      \
        num = segred8(num);                                                    \
        den = segred8(den);                                                    \
        const float z = num / den;           /* valid in all 8 seg lanes */    \
        __VA_ARGS__                                                            \
    }

    // ======= LAYER 0 =======
    LAYER_PASS(xs, sc[6] * LOG2E, 0.f, xs, sc[7] * LOG2E, p0s, xs,
        { if (dok && sub == 0) ys[d] = z; });
    __syncthreads();

    // ======= LAYER 1 (+ fused layer-2 per-node scalars, segmented dots) ====
    LAYER_PASS(ys, sc[9] * LOG2E, sc[11] * LOG2E, ys, sc[10] * LOG2E, p1s, ys,
        {
            float t0 = 0.f;
            float t1 = 0.f;
            float t2 = 0.f;
            _Pragma("unroll")
            for (int j = 0; j < 4; j++) {
                const int c = sub + 8 * j;
                float h = fmaxf(z * w01v[c] + Bv[c], 0.f);
                t0 += h * usv[c]; t1 += h * udv[c]; t2 += h * vvv[c];
            }
            t0 = segred8(t0); t1 = segred8(t1); t2 = segred8(t2);
            if (dok && sub == 0) { hs2[d] = t0; hd2[d] = t1; ctr[d] = t2; }
        });
    __syncthreads();

    // ======= LAYER 2 (per-warp head partials) =======
    LAYER_PASS(hs2, LOG2E, 0.f, hd2, LOG2E, p2s, ctr,
        {
            float q = (dok && sub == 0) ? z : 0.f;
            q = wredsum(q);
            if (lane == 0) wsum[w] = q;
        });
    __syncthreads();

    // ======= head: out[g] = relu( sum + 111*(b2.linW) + linb ) =======
    if (w == 0) {
        float t = wredsum((lane < NW) ? wsum[lane] : 0.f);
        if (lane == 0) {
            float v = t + 111.f * sc[8] + linb[0];
            out[g] = (v > 0.f) ? v : 0.f;
        }
    }
#undef LAYER_PASS
}

static constexpr int SMEM_FLOATS =
    3 * 112 * PD + 5 * 112 + 32 + 5 * 32 + 16;
static constexpr int SMEM_BYTES = SMEM_FLOATS * 4;   // ~155 KB

extern "C" void kernel_launch(void* const* d_in, const int* in_sizes, int n_in,
                              void* d_out, int out_size)
{
    const float* x    = (const float*)d_in[0];
    // d_in[1] = edge_index: structure fully determined, never read.
    const float* ea   = (const float*)d_in[2];

    const float* W0  = (const float*)d_in[3];
    const float* as0 = (const float*)d_in[4];
    const float* ad0 = (const float*)d_in[5];
    const float* We0 = (const float*)d_in[6];
    const float* ae0 = (const float*)d_in[7];
    const float* b0  = (const float*)d_in[8];

    const float* W1  = (const float*)d_in[9];
    const float* as1 = (const float*)d_in[10];
    const float* ad1 = (const float*)d_in[11];
    const float* We1 = (const float*)d_in[12];
    const float* ae1 = (const float*)d_in[13];
    const float* b1  = (const float*)d_in[14];

    const float* W2  = (const float*)d_in[15];
    const float* as2 = (const float*)d_in[16];
    const float* ad2 = (const float*)d_in[17];
    const float* We2 = (const float*)d_in[18];
    const float* ae2 = (const float*)d_in[19];
    const float* b2  = (const float*)d_in[20];

    const float* linW = (const float*)d_in[21];
    const float* linb = (const float*)d_in[22];
    float* out = (float*)d_out;

    cudaFuncSetAttribute(fused_all, cudaFuncAttributeMaxDynamicSharedMemorySize, SMEM_BYTES);
    fused_all<<<NB, NT, SMEM_BYTES>>>(x, ea,
                                      W0, as0, ad0, We0, ae0, b0,
                                      W1, as1, ad1, We1, ae1, b1,
                                      W2, as2, ad2, We2, ae2, b2,
                                      linW, linb, out);
}